// round 2
// baseline (speedup 1.0000x reference)
#include <cuda_runtime.h>

#define BATCH 2
#define NSEQ 2048
#define DMODEL 1024
#define NHEAD 16
#define DHEAD 64
#define ATT_SCALE 0.125f   // 1/sqrt(64)
#define NEG_BIG (-1e30f)

// Scratch (allocation-free: __device__ globals)
__device__ float g_q[(size_t)BATCH * NHEAD * NSEQ * DHEAD];   // [b,h,n,dh]
__device__ float g_k[(size_t)BATCH * NHEAD * NSEQ * DHEAD];
__device__ float g_v[(size_t)BATCH * NHEAD * NSEQ * DHEAD];
__device__ float g_y[(size_t)BATCH * NSEQ * DMODEL];          // [b,n,d]

// ===========================================================================
// Dense NT sgemm core: C[m][c] = sum_k A[m][k] * B[c][k], K = 1024.
// 128x128 tile, 256 threads, 8x8 microtile, double-buffered k=8 stages.
// Epilogue differs per use -> two kernels sharing the same body via macro.
// ===========================================================================
#define GEMM_BODY(APTR, BPTR)                                                  \
    __shared__ __align__(16) float As[2][8][128];                              \
    __shared__ __align__(16) float Bs[2][8][128];                              \
    const int tid = threadIdx.x;                                               \
    const int tx = tid & 15, ty = tid >> 4;                                    \
    const int mBase = blockIdx.y << 7;                                         \
    const int cBase = blockIdx.x << 7;                                         \
    const int lm = tid >> 1;            /* 0..127 */                           \
    const int lk = (tid & 1) << 2;      /* 0 or 4 */                           \
    const float* aptr = (APTR) + (size_t)(mBase + lm) * DMODEL + lk;           \
    const float* bptr = (BPTR) + (size_t)(cBase + lm) * DMODEL + lk;           \
    {                                                                          \
        float4 a4 = *(const float4*)aptr;                                      \
        float4 b4 = *(const float4*)bptr;                                      \
        As[0][lk + 0][lm] = a4.x; As[0][lk + 1][lm] = a4.y;                    \
        As[0][lk + 2][lm] = a4.z; As[0][lk + 3][lm] = a4.w;                    \
        Bs[0][lk + 0][lm] = b4.x; Bs[0][lk + 1][lm] = b4.y;                    \
        Bs[0][lk + 2][lm] = b4.z; Bs[0][lk + 3][lm] = b4.w;                    \
    }                                                                          \
    __syncthreads();                                                           \
    float acc[8][8] = {};                                                      \
    int buf = 0;                                                               \
    for (int kt = 1; kt <= DMODEL / 8; kt++) {                                 \
        float4 na, nb;                                                         \
        if (kt < DMODEL / 8) {                                                 \
            na = *(const float4*)(aptr + kt * 8);                              \
            nb = *(const float4*)(bptr + kt * 8);                              \
        }                                                                      \
        _Pragma("unroll")                                                      \
        for (int k = 0; k < 8; k++) {                                          \
            float4 a0 = *(const float4*)&As[buf][k][ty << 3];                  \
            float4 a1 = *(const float4*)&As[buf][k][(ty << 3) + 4];            \
            float4 b0 = *(const float4*)&Bs[buf][k][tx << 3];                  \
            float4 b1 = *(const float4*)&Bs[buf][k][(tx << 3) + 4];            \
            float ar[8] = {a0.x, a0.y, a0.z, a0.w, a1.x, a1.y, a1.z, a1.w};    \
            float br[8] = {b0.x, b0.y, b0.z, b0.w, b1.x, b1.y, b1.z, b1.w};    \
            _Pragma("unroll")                                                  \
            for (int i = 0; i < 8; i++) {                                      \
                _Pragma("unroll")                                              \
                for (int j = 0; j < 8; j++) acc[i][j] += ar[i] * br[j];        \
            }                                                                  \
        }                                                                      \
        if (kt < DMODEL / 8) {                                                 \
            int nxt = buf ^ 1;                                                 \
            As[nxt][lk + 0][lm] = na.x; As[nxt][lk + 1][lm] = na.y;            \
            As[nxt][lk + 2][lm] = na.z; As[nxt][lk + 3][lm] = na.w;            \
            Bs[nxt][lk + 0][lm] = nb.x; Bs[nxt][lk + 1][lm] = nb.y;            \
            Bs[nxt][lk + 2][lm] = nb.z; Bs[nxt][lk + 3][lm] = nb.w;            \
            __syncthreads();                                                   \
            buf = nxt;                                                         \
        }                                                                      \
    }

// ---------------------------------------------------------------------------
// Kernel 1: qkv = x @ Wqkv^T, scattered into g_q/g_k/g_v in [b,h,n,dh] layout.
// grid (3072/128, 4096/128) = (24, 32)
// ---------------------------------------------------------------------------
__global__ __launch_bounds__(256) void qkv_kernel(const float* __restrict__ x,
                                                  const float* __restrict__ W) {
    GEMM_BODY(x, W)

    // c0..c0+7 stays within one (three, h) group: c0 multiple of 8, 64 | group
    const int c0 = cBase + (tx << 3);
    const int three = c0 >> 10;
    const int hh = (c0 >> 6) & (NHEAD - 1);
    const int dh0 = c0 & 63;
    float* dst = (three == 0) ? g_q : (three == 1) ? g_k : g_v;
#pragma unroll
    for (int i = 0; i < 8; i++) {
        int m = mBase + (ty << 3) + i;
        int b = m >> 11;            // m / NSEQ
        int n = m & (NSEQ - 1);
        size_t base = (((size_t)(b * NHEAD + hh) * NSEQ + n) << 6) + dh0;
        *(float4*)&dst[base]     = make_float4(acc[i][0], acc[i][1], acc[i][2], acc[i][3]);
        *(float4*)&dst[base + 4] = make_float4(acc[i][4], acc[i][5], acc[i][6], acc[i][7]);
    }
}

// ---------------------------------------------------------------------------
// Kernel 3: out = y @ Wproj^T + bproj.   grid (1024/128, 4096/128) = (8, 32)
// ---------------------------------------------------------------------------
__global__ __launch_bounds__(256) void proj_kernel(const float* __restrict__ Wp,
                                                   const float* __restrict__ bproj,
                                                   float* __restrict__ out) {
    GEMM_BODY(g_y, Wp)

    const int c0 = cBase + (tx << 3);
    float4 bb0 = *(const float4*)&bproj[c0];
    float4 bb1 = *(const float4*)&bproj[c0 + 4];
#pragma unroll
    for (int i = 0; i < 8; i++) {
        int m = mBase + (ty << 3) + i;
        *(float4*)&out[(size_t)m * DMODEL + c0] =
            make_float4(acc[i][0] + bb0.x, acc[i][1] + bb0.y,
                        acc[i][2] + bb0.z, acc[i][3] + bb0.w);
        *(float4*)&out[(size_t)m * DMODEL + c0 + 4] =
            make_float4(acc[i][4] + bb1.x, acc[i][5] + bb1.y,
                        acc[i][6] + bb1.z, acc[i][7] + bb1.w);
    }
}

// ---------------------------------------------------------------------------
// Kernel 2: flash attention with bias + key-padding mask (unchanged from R0).
// grid.x = q-tile (N/64), grid.y = b*H + h. 256 threads.
// smem: qs[64][64] (r,dh) | kst[64][64] (dh,j) | vs[64][64] (j,dh) | ps[64][64] (r,j)
// ---------------------------------------------------------------------------
__global__ __launch_bounds__(256) void attn_kernel(const float* __restrict__ attn_bias,
                                                   const unsigned int* __restrict__ mask) {
    extern __shared__ __align__(16) float sm[];
    float* qs  = sm;             // 4096
    float* kst = sm + 4096;      // 4096
    float* vs  = sm + 8192;      // 4096
    float* ps  = sm + 12288;     // 4096

    const int tid = threadIdx.x;
    const int tx = tid & 15, ty = tid >> 4;
    const int q0 = blockIdx.x << 6;
    const int bh = blockIdx.y;
    const int b = bh >> 4, h = bh & 15;

    const float* qg = g_q + (size_t)bh * NSEQ * DHEAD;
    const float* kg = g_k + (size_t)bh * NSEQ * DHEAD;
    const float* vg = g_v + (size_t)bh * NSEQ * DHEAD;
    const float* biasg = attn_bias + ((size_t)b * NSEQ + q0) * NSEQ;
    const unsigned int* maskg = mask + b * NSEQ;

    // Load Q tile (1024 float4 / 256 threads)
#pragma unroll
    for (int t = 0; t < 4; t++) {
        int p = tid + t * 256;
        int r = p >> 4, ch = (p & 15) << 2;
        *(float4*)&qs[r * 64 + ch] = *(const float4*)&qg[(size_t)(q0 + r) * 64 + ch];
    }

    float m_i[4], l_i[4], o[4][4];
#pragma unroll
    for (int i = 0; i < 4; i++) {
        m_i[i] = NEG_BIG; l_i[i] = 0.0f;
        o[i][0] = o[i][1] = o[i][2] = o[i][3] = 0.0f;
    }
    const int r0 = ty << 2;
    const int c0 = tx << 2;
    const int jrow = tid >> 2;          // 0..63 (load mapping)
    const int dc   = (tid & 3) << 2;    // 0,4,8,12

    for (int kt = 0; kt < NSEQ / 64; kt++) {
        const int kb = kt << 6;
        // Prefix mask: first key masked => tile (and all later tiles) fully masked.
        if (maskg[kb] == 0u) break;

        // Load K (to transpose) and V tiles
        float4 kv4[4], vv4[4];
#pragma unroll
        for (int u = 0; u < 4; u++) {
            kv4[u] = *(const float4*)&kg[(size_t)(kb + jrow) * 64 + dc + u * 16];
            vv4[u] = *(const float4*)&vg[(size_t)(kb + jrow) * 64 + dc + u * 16];
        }
        __syncthreads();   // previous PV finished reading vs/ps
#pragma unroll
        for (int u = 0; u < 4; u++) {
            int dh = dc + u * 16;
            kst[(dh + 0) * 64 + jrow] = kv4[u].x;
            kst[(dh + 1) * 64 + jrow] = kv4[u].y;
            kst[(dh + 2) * 64 + jrow] = kv4[u].z;
            kst[(dh + 3) * 64 + jrow] = kv4[u].w;
            *(float4*)&vs[jrow * 64 + dh] = vv4[u];
        }
        __syncthreads();

        // S = Q K^T for this tile
        float s[4][4] = {};
#pragma unroll
        for (int dh = 0; dh < 64; dh += 4) {
            float4 qv[4];
#pragma unroll
            for (int i = 0; i < 4; i++) qv[i] = *(const float4*)&qs[(r0 + i) * 64 + dh];
#pragma unroll
            for (int w = 0; w < 4; w++) {
                float4 kk = *(const float4*)&kst[(dh + w) * 64 + c0];
#pragma unroll
                for (int i = 0; i < 4; i++) {
                    float qq = (w == 0) ? qv[i].x : (w == 1) ? qv[i].y : (w == 2) ? qv[i].z : qv[i].w;
                    s[i][0] += qq * kk.x; s[i][1] += qq * kk.y;
                    s[i][2] += qq * kk.z; s[i][3] += qq * kk.w;
                }
            }
        }

        // scale + bias + mask
        uint4 mk = *(const uint4*)&maskg[kb + c0];
#pragma unroll
        for (int i = 0; i < 4; i++) {
            float4 bb = *(const float4*)&biasg[(size_t)(r0 + i) * NSEQ + kb + c0];
            s[i][0] = mk.x ? (s[i][0] * ATT_SCALE + bb.x) : NEG_BIG;
            s[i][1] = mk.y ? (s[i][1] * ATT_SCALE + bb.y) : NEG_BIG;
            s[i][2] = mk.z ? (s[i][2] * ATT_SCALE + bb.z) : NEG_BIG;
            s[i][3] = mk.w ? (s[i][3] * ATT_SCALE + bb.w) : NEG_BIG;
        }

        // online softmax (row reduction across 16 tx-lanes)
#pragma unroll
        for (int i = 0; i < 4; i++) {
            float mx = fmaxf(fmaxf(s[i][0], s[i][1]), fmaxf(s[i][2], s[i][3]));
            mx = fmaxf(mx, __shfl_xor_sync(0xffffffffu, mx, 1));
            mx = fmaxf(mx, __shfl_xor_sync(0xffffffffu, mx, 2));
            mx = fmaxf(mx, __shfl_xor_sync(0xffffffffu, mx, 4));
            mx = fmaxf(mx, __shfl_xor_sync(0xffffffffu, mx, 8));
            float mnew = fmaxf(m_i[i], mx);
            float alpha = __expf(m_i[i] - mnew);
            float p0 = __expf(s[i][0] - mnew);
            float p1 = __expf(s[i][1] - mnew);
            float p2 = __expf(s[i][2] - mnew);
            float p3 = __expf(s[i][3] - mnew);
            float rs = p0 + p1 + p2 + p3;
            rs += __shfl_xor_sync(0xffffffffu, rs, 1);
            rs += __shfl_xor_sync(0xffffffffu, rs, 2);
            rs += __shfl_xor_sync(0xffffffffu, rs, 4);
            rs += __shfl_xor_sync(0xffffffffu, rs, 8);
            l_i[i] = l_i[i] * alpha + rs;
            m_i[i] = mnew;
            o[i][0] *= alpha; o[i][1] *= alpha; o[i][2] *= alpha; o[i][3] *= alpha;
            *(float4*)&ps[(r0 + i) * 64 + c0] = make_float4(p0, p1, p2, p3);
        }
        __syncthreads();

        // O += P V (reduction over j)
#pragma unroll
        for (int j = 0; j < 64; j += 4) {
            float4 pv[4];
#pragma unroll
            for (int i = 0; i < 4; i++) pv[i] = *(const float4*)&ps[(r0 + i) * 64 + j];
#pragma unroll
            for (int w = 0; w < 4; w++) {
                float4 vv = *(const float4*)&vs[(j + w) * 64 + c0];
#pragma unroll
                for (int i = 0; i < 4; i++) {
                    float pp = (w == 0) ? pv[i].x : (w == 1) ? pv[i].y : (w == 2) ? pv[i].z : pv[i].w;
                    o[i][0] += pp * vv.x; o[i][1] += pp * vv.y;
                    o[i][2] += pp * vv.z; o[i][3] += pp * vv.w;
                }
            }
        }
        // top-of-loop __syncthreads() protects kst/vs/ps for next tile
    }

    // epilogue: normalize, write y in [b,n,d] layout (d = h*64 + c0..)
#pragma unroll
    for (int i = 0; i < 4; i++) {
        float inv = 1.0f / l_i[i];
        float4 r = make_float4(o[i][0] * inv, o[i][1] * inv, o[i][2] * inv, o[i][3] * inv);
        *(float4*)&g_y[((size_t)(b * NSEQ) + q0 + r0 + i) * DMODEL + h * 64 + c0] = r;
    }
}

// ---------------------------------------------------------------------------
extern "C" void kernel_launch(void* const* d_in, const int* in_sizes, int n_in,
                              void* d_out, int out_size) {
    const float* x          = (const float*)d_in[0];
    const float* attn_bias  = (const float*)d_in[1];
    const unsigned int* msk = (const unsigned int*)d_in[2];
    const float* Wqkv       = (const float*)d_in[3];
    const float* Wproj      = (const float*)d_in[4];
    const float* bproj      = (const float*)d_in[5];
    float* out = (float*)d_out;

    (void)in_sizes; (void)n_in; (void)out_size;

    // 64 KB dynamic smem for the attention kernel (over the 48 KB default).
    cudaFuncSetAttribute((const void*)attn_kernel,
                         cudaFuncAttributeMaxDynamicSharedMemorySize, 65536);

    qkv_kernel<<<dim3(24, 32), 256>>>(x, Wqkv);
    attn_kernel<<<dim3(NSEQ / 64, BATCH * NHEAD), 256, 65536>>>(attn_bias, msk);
    proj_kernel<<<dim3(8, 32), 256>>>(Wproj, bproj, out);
}